// round 16
// baseline (speedup 1.0000x reference)
#include <cuda_runtime.h>
#include <cstdint>
#include <math.h>

#define BB 4
#define TT 2048
#define DD 1024
#define MTOT (BB * TT)
#define SCALE (0.03125f)
#define THREADS 512

// ---------------- scratch (no allocations allowed) ----------------
__device__ float g_xpk[(size_t)MTOT * DD];     // x, A-frag packed, tf32
__device__ float g_wpk[(size_t)3 * DD * DD];   // W, B-frag packed, tf32
__device__ float g_qpk[(size_t)MTOT * DD];     // Q, A-frag packed (global m)
__device__ float g_kpk[(size_t)MTOT * DD];     // K, B-frag packed per batch (n=t,k=e)
__device__ float g_vpk[(size_t)MTOT * DD];     // V, B-frag packed per batch (n=e,k=t)
__device__ float g_s[(size_t)BB * TT * TT];    // scores -> att (tf32-rounded)

// ---------------- helpers ----------------
__device__ __forceinline__ uint32_t f2tf(float x) {
    uint32_t u;
    asm("cvt.rna.tf32.f32 %0, %1;" : "=r"(u) : "f"(x));
    return u;
}
__device__ __forceinline__ float roundtf(float x) {
    return __uint_as_float(f2tf(x));
}
__device__ __forceinline__ void mma_tf32(float* c, const uint32_t* a, const uint32_t* b) {
    asm volatile(
        "mma.sync.aligned.m16n8k8.row.col.f32.tf32.tf32.f32 "
        "{%0,%1,%2,%3}, {%4,%5,%6,%7}, {%8,%9}, {%0,%1,%2,%3};"
        : "+f"(c[0]), "+f"(c[1]), "+f"(c[2]), "+f"(c[3])
        : "r"(a[0]), "r"(a[1]), "r"(a[2]), "r"(a[3]), "r"(b[0]), "r"(b[1]));
}
__device__ __forceinline__ uint32_t smem_u32(const void* p) {
    uint32_t a;
    asm("{ .reg .u64 t; cvta.to.shared.u64 t, %1; cvt.u32.u64 %0, t; }" : "=r"(a) : "l"(p));
    return a;
}
__device__ __forceinline__ void cpa16(uint32_t* dst, const float* src) {
    asm volatile("cp.async.cg.shared.global [%0], [%1], 16;"
                 :: "r"(smem_u32(dst)), "l"(src));
}
#define CP_COMMIT() asm volatile("cp.async.commit_group;" ::: "memory")
#define CP_WAIT1()  asm volatile("cp.async.wait_group 1;" ::: "memory")

#define KC 16
#define DSTAGES 3
#define SA 20
#define A_CL_WORDS (128 * SA)            // 2560 classic A tile
#define PK_CHUNK 2048
#define PK_PANEL64 (64 * PK_CHUNK)       // K-range 1024
#define PK_PANEL128 (128 * PK_CHUNK)     // K-range 2048

// packed-layout address helpers (element granularity)
__device__ __forceinline__ size_t apk_off(int m, int k) {
    return ((size_t)(m >> 7) * 64 + (k >> 4)) * PK_CHUNK
         + (size_t)(((k >> 3) & 1) * 1024 + ((m >> 4) & 7) * 128
         + ((m & 7) * 4 + (k & 3)) * 4
         + ((m >> 3) & 1) + 2 * ((k >> 2) & 1));
}
__device__ __forceinline__ size_t bpk_off(int n, int k, int nchunks) {
    return ((size_t)(n >> 7) * nchunks + (k >> 4)) * PK_CHUNK
         + (size_t)(((k >> 3) & 1) * 1024 + ((n >> 4) & 7) * 128
         + ((n & 7) * 4 + (k & 3)) * 4
         + ((k >> 2) & 1) + 2 * ((n >> 3) & 1));
}

// ==========  fully-packed 128x256 GEMM mainloop (512 thr, 2Mx8N warps) ======
#define AW 2048                       // packed A chunk words
#define BW 4096                       // packed B chunk words (2 panels)
#define GW (AW + BW)                  // 6144
#define GDW (2 * GW)                  // double chunk 12288
#define GSMEM_BYTES (DSTAGES * GDW * 4)   // 147456

// nc chunks (even); Bpk panels p0 at Bpk, p1 at Bpk + pstride.
__device__ __forceinline__ void gemm_pk2_main(
    const float* __restrict__ Apk, const float* __restrict__ Bpk, size_t pstride,
    int nc, float acc[4][4][4], int wm, int wn, int lane)
{
    extern __shared__ uint32_t dsm[];
    const int tid = threadIdx.x;

#pragma unroll
    for (int mi = 0; mi < 4; mi++)
#pragma unroll
        for (int ni = 0; ni < 4; ni++)
#pragma unroll
            for (int j = 0; j < 4; j++) acc[mi][ni][j] = 0.f;

    const int ndc = nc >> 1;

    auto issue2 = [&](int d) {
        uint32_t* st = dsm + (d % DSTAGES) * GDW;
#pragma unroll
        for (int h = 0; h < 2; h++) {
            const int c = 2 * d + h;
            uint32_t* s2 = st + h * GW;
            cpa16(s2 + tid * 4, Apk + (size_t)c * PK_CHUNK + tid * 4);
#pragma unroll
            for (int pn = 0; pn < 2; pn++)
                cpa16(s2 + AW + pn * 2048 + tid * 4,
                      Bpk + (size_t)pn * pstride + (size_t)c * PK_CHUNK + tid * 4);
        }
        CP_COMMIT();
    };

    issue2(0);
    issue2(1);

    for (int d = 0; d < ndc; d++) {
        CP_WAIT1();
        __syncthreads();
        if (d + 2 < ndc) issue2(d + 2);
        const uint32_t* stage = dsm + (d % DSTAGES) * GDW;

#pragma unroll
        for (int h = 0; h < 2; h++) {
            const uint32_t* As = stage + h * GW;
            const uint32_t* Bs = As + AW;
#pragma unroll
            for (int s = 0; s < 2; s++) {
                uint4 af[4];
#pragma unroll
                for (int mi = 0; mi < 4; mi++)
                    af[mi] = *reinterpret_cast<const uint4*>(
                        As + s * 1024 + (wm * 4 + mi) * 128 + lane * 4);
#pragma unroll
                for (int p = 0; p < 2; p++) {
                    const int nb = wn * 2 + p;
                    uint4 bq = *reinterpret_cast<const uint4*>(
                        Bs + (nb >> 3) * 2048 + s * 1024 + (nb & 7) * 128 + lane * 4);
                    const uint32_t* bw = reinterpret_cast<const uint32_t*>(&bq);
#pragma unroll
                    for (int sub = 0; sub < 2; sub++)
#pragma unroll
                        for (int mi = 0; mi < 4; mi++)
                            mma_tf32(acc[mi][2 * p + sub],
                                     reinterpret_cast<const uint32_t*>(&af[mi]),
                                     bw + sub * 2);
                }
            }
        }
    }
}

// ===================  proj: packed in, packed out  ==========================
__global__ void __launch_bounds__(THREADS, 1)
proj_mma_pk()
{
    const int z = blockIdx.z;
    const float* Apk = g_xpk + (size_t)blockIdx.y * PK_PANEL64;
    const float* Bpk = g_wpk + (size_t)z * (8 * PK_PANEL64)
                     + (size_t)(2 * blockIdx.x) * PK_PANEL64;

    const int tid = threadIdx.x;
    const int wid = tid >> 5, lane = tid & 31;
    const int g = lane >> 2, t = lane & 3;
    const int wm = wid & 1;
    const int wn = wid >> 1;

    float acc[4][4][4];
    gemm_pk2_main(Apk, Bpk, PK_PANEL64, DD / KC, acc, wm, wn, lane);

    const int Mb = blockIdx.y * 128;
    const int Nb = blockIdx.x * 256;
    const int b = blockIdx.y >> 4;
    const int MbL = (blockIdx.y & 15) * 128;

#pragma unroll
    for (int mi = 0; mi < 4; mi++) {
        const int r0 = wm * 64 + mi * 16 + g;
#pragma unroll
        for (int ni = 0; ni < 4; ni++) {
            const int c0 = wn * 32 + (ni >> 1) * 16 + (ni & 1) * 8 + 2 * t;
            float v0 = roundtf(acc[mi][ni][0]);
            float v1 = roundtf(acc[mi][ni][1]);
            float v2 = roundtf(acc[mi][ni][2]);
            float v3 = roundtf(acc[mi][ni][3]);
            if (z == 0) {
                const int m0 = Mb + r0, k0 = Nb + c0;
                g_qpk[apk_off(m0, k0)]         = v0;
                g_qpk[apk_off(m0, k0 + 1)]     = v1;
                g_qpk[apk_off(m0 + 8, k0)]     = v2;
                g_qpk[apk_off(m0 + 8, k0 + 1)] = v3;
            } else if (z == 1) {
                float* base = g_kpk + (size_t)b * TT * DD;
                const int n0 = MbL + r0, k0 = Nb + c0;
                base[bpk_off(n0, k0, 64)]         = v0;
                base[bpk_off(n0, k0 + 1, 64)]     = v1;
                base[bpk_off(n0 + 8, k0, 64)]     = v2;
                base[bpk_off(n0 + 8, k0 + 1, 64)] = v3;
            } else {
                float* base = g_vpk + (size_t)b * TT * DD;
                const int k0 = MbL + r0, n0 = Nb + c0;
                base[bpk_off(n0, k0, 128)]         = v0;
                base[bpk_off(n0 + 1, k0, 128)]     = v1;
                base[bpk_off(n0, k0 + 8, 128)]     = v2;
                base[bpk_off(n0 + 1, k0 + 8, 128)] = v3;
            }
        }
    }
}

// ===================  scores: fully packed, 128x256 tile  ===================
__global__ void __launch_bounds__(THREADS, 1)
scores_mma()
{
    if (2 * blockIdx.x > blockIdx.y) return;   // fully masked 128x256 tile
    const int b = blockIdx.z;
    const float* Apk = g_qpk + (size_t)(b * 16 + blockIdx.y) * PK_PANEL64;
    const float* Bpk = g_kpk + (size_t)b * TT * DD
                     + (size_t)(2 * blockIdx.x) * PK_PANEL64;
    float* C = g_s + (size_t)b * TT * TT
             + (size_t)blockIdx.y * 128 * TT + blockIdx.x * 256;

    const int tid = threadIdx.x;
    const int wid = tid >> 5, lane = tid & 31;
    const int g = lane >> 2, t = lane & 3;
    const int wm = wid & 1;
    const int wn = wid >> 1;

    float acc[4][4][4];
    gemm_pk2_main(Apk, Bpk, PK_PANEL64, DD / KC, acc, wm, wn, lane);

#pragma unroll
    for (int mi = 0; mi < 4; mi++) {
        const int r0 = wm * 64 + mi * 16 + g;
#pragma unroll
        for (int ni = 0; ni < 4; ni++) {
            const int col = wn * 32 + (ni >> 1) * 16 + (ni & 1) * 8 + 2 * t;
            float2 v0, v1;
            v0.x = acc[mi][ni][0] * SCALE; v0.y = acc[mi][ni][1] * SCALE;
            v1.x = acc[mi][ni][2] * SCALE; v1.y = acc[mi][ni][3] * SCALE;
            *reinterpret_cast<float2*>(C + (size_t)r0 * TT + col) = v0;
            *reinterpret_cast<float2*>(C + (size_t)(r0 + 8) * TT + col) = v1;
        }
    }
}

// ============  pv: hybrid (classic att A + packed V B), 128x256  ============
#define HW (A_CL_WORDS + BW)              // 6656 words per chunk
#define HDW (2 * HW)                      // 13312
#define HSMEM_BYTES (DSTAGES * HDW * 4)   // 159744

__global__ void __launch_bounds__(THREADS, 1)
pv_mma(float* __restrict__ out)
{
    extern __shared__ uint32_t dsm[];
    const int b = blockIdx.z;
    const size_t qb = (size_t)blockIdx.y * 128;
    const float* A = g_s + (size_t)b * TT * TT + qb * TT;      // [q][t]
    const float* Bpk = g_vpk + (size_t)b * TT * DD
                     + (size_t)(2 * blockIdx.x) * PK_PANEL128;
    float* C = out + (size_t)b * TT * DD + qb * DD + blockIdx.x * 256;

    const int tid = threadIdx.x;
    const int wid = tid >> 5, lane = tid & 31;
    const int g = lane >> 2, t = lane & 3;
    const int wm = wid & 1;
    const int wn = wid >> 1;

    const int rowA = tid >> 2;
    const int kqA = (tid & 3) * 4;

    float acc[4][4][4];
#pragma unroll
    for (int mi = 0; mi < 4; mi++)
#pragma unroll
        for (int ni = 0; ni < 4; ni++)
#pragma unroll
            for (int j = 0; j < 4; j++) acc[mi][ni][j] = 0.f;

    const int ndc = (blockIdx.y + 1) * 4;   // causal bound / 32, >= 4

    auto issue2 = [&](int d) {
        uint32_t* st = dsm + (d % DSTAGES) * HDW;
#pragma unroll
        for (int h = 0; h < 2; h++) {
            const int c = 2 * d + h;
            const int k0 = c * KC;
            uint32_t* s2 = st + h * HW;
            cpa16(s2 + rowA * SA + kqA, A + (size_t)rowA * TT + k0 + kqA);
            uint32_t* bt = s2 + A_CL_WORDS;
#pragma unroll
            for (int pn = 0; pn < 2; pn++)
                cpa16(bt + pn * 2048 + tid * 4,
                      Bpk + (size_t)pn * PK_PANEL128 + (size_t)c * PK_CHUNK + tid * 4);
        }
        CP_COMMIT();
    };

    issue2(0);
    issue2(1);

    for (int d = 0; d < ndc; d++) {
        CP_WAIT1();
        __syncthreads();
        if (d + 2 < ndc) issue2(d + 2);
        const uint32_t* stage = dsm + (d % DSTAGES) * HDW;

#pragma unroll
        for (int h = 0; h < 2; h++) {
            const uint32_t* As = stage + h * HW;
            const uint32_t* Bs = As + A_CL_WORDS;
#pragma unroll
            for (int s = 0; s < 2; s++) {
                const int ks = s * 8;
                uint32_t af[4][4];
#pragma unroll
                for (int mi = 0; mi < 4; mi++) {
                    const int r = wm * 64 + mi * 16 + g;
                    af[mi][0] = As[r * SA + ks + t];
                    af[mi][1] = As[(r + 8) * SA + ks + t];
                    af[mi][2] = As[r * SA + ks + t + 4];
                    af[mi][3] = As[(r + 8) * SA + ks + t + 4];
                }
#pragma unroll
                for (int p = 0; p < 2; p++) {
                    const int nb = wn * 2 + p;
                    uint4 bq = *reinterpret_cast<const uint4*>(
                        Bs + (nb >> 3) * 2048 + s * 1024 + (nb & 7) * 128 + lane * 4);
                    const uint32_t* bw = reinterpret_cast<const uint32_t*>(&bq);
#pragma unroll
                    for (int sub = 0; sub < 2; sub++)
#pragma unroll
                        for (int mi = 0; mi < 4; mi++)
                            mma_tf32(acc[mi][2 * p + sub], af[mi], bw + sub * 2);
                }
            }
        }
    }

#pragma unroll
    for (int mi = 0; mi < 4; mi++) {
        const int r0 = wm * 64 + mi * 16 + g;
#pragma unroll
        for (int ni = 0; ni < 4; ni++) {
            const int col = wn * 32 + (ni >> 1) * 16 + (ni & 1) * 8 + 2 * t;
            float2 v0, v1;
            v0.x = acc[mi][ni][0]; v0.y = acc[mi][ni][1];
            v1.x = acc[mi][ni][2]; v1.y = acc[mi][ni][3];
            *reinterpret_cast<float2*>(C + (size_t)r0 * DD + col) = v0;
            *reinterpret_cast<float2*>(C + (size_t)(r0 + 8) * DD + col) = v1;
        }
    }
}

// ---------------------------------------------------------------------------
// Pre-pack passes (x, W)
// ---------------------------------------------------------------------------
__global__ void __launch_bounds__(256)
pack_x_kernel(const float* __restrict__ x)
{
    const int idx = blockIdx.x * 256 + threadIdx.x;
    const int lane = idx & 31;
    const int blk = idx >> 5;
    const int kb = blk & 127;
    const int mb = blk >> 7;
    const int m0 = mb * 16, k0 = kb * 8;
    const int g = lane >> 2, t = lane & 3;

    float4 v;
    v.x = roundtf(x[(size_t)(m0 + g) * DD + k0 + t]);
    v.y = roundtf(x[(size_t)(m0 + g + 8) * DD + k0 + t]);
    v.z = roundtf(x[(size_t)(m0 + g) * DD + k0 + t + 4]);
    v.w = roundtf(x[(size_t)(m0 + g + 8) * DD + k0 + t + 4]);

    const int panel = mb >> 3, mbl = mb & 7, chunk = kb >> 1, slab = kb & 1;
    const size_t off = (size_t)(panel * 64 + chunk) * PK_CHUNK
                     + slab * 1024 + mbl * 128 + lane * 4;
    *reinterpret_cast<float4*>(g_xpk + off) = v;
}

__global__ void __launch_bounds__(256)
pack_w_kernel(const float* __restrict__ Wq, const float* __restrict__ Wk,
              const float* __restrict__ Wv)
{
    const int z = blockIdx.y;
    const float* W = (z == 0) ? Wq : (z == 1) ? Wk : Wv;
    const int idx = blockIdx.x * 256 + threadIdx.x;
    const int lane = idx & 31;
    const int blk = idx >> 5;
    const int kb = blk & 127;
    const int nbp = blk >> 7;
    const int k0 = kb * 8, n0 = nbp * 16;
    const int gn = lane >> 2, tk = lane & 3;

    float4 v;
    v.x = roundtf(W[(size_t)(k0 + tk) * DD + n0 + gn]);
    v.y = roundtf(W[(size_t)(k0 + tk + 4) * DD + n0 + gn]);
    v.z = roundtf(W[(size_t)(k0 + tk) * DD + n0 + 8 + gn]);
    v.w = roundtf(W[(size_t)(k0 + tk + 4) * DD + n0 + 8 + gn]);

    const int panel = nbp >> 3, nbl = nbp & 7, chunk = kb >> 1, slab = kb & 1;
    const size_t off = (size_t)z * (8 * PK_PANEL64)
                     + (size_t)(panel * 64 + chunk) * PK_CHUNK
                     + slab * 1024 + nbl * 128 + lane * 4;
    *reinterpret_cast<float4*>(g_wpk + off) = v;
}

// ---------------------------------------------------------------------------
// Causal softmax, float4 path (in-place on g_s)
// ---------------------------------------------------------------------------
__global__ void __launch_bounds__(256)
softmax_kernel()
{
    const int row = blockIdx.x;
    const int q = row % TT;
    const int n = q + 1;
    float4* s4 = reinterpret_cast<float4*>(g_s + (size_t)row * TT);
    const int tid = threadIdx.x;
    __shared__ float red[256];

    float4 v[2];
    float m = -INFINITY;
#pragma unroll
    for (int i = 0; i < 2; i++) {
        const int idx4 = tid + i * 256;
        v[i] = s4[idx4];
        float* pv = reinterpret_cast<float*>(&v[i]);
        const int base = idx4 * 4;
#pragma unroll
        for (int j = 0; j < 4; j++) {
            if (base + j >= n) pv[j] = -INFINITY;
            else m = fmaxf(m, pv[j]);
        }
    }
    red[tid] = m;
    __syncthreads();
    for (int off = 128; off > 0; off >>= 1) {
        if (tid < off) red[tid] = fmaxf(red[tid], red[tid + off]);
        __syncthreads();
    }
    m = red[0];
    __syncthreads();

    float sum = 0.f;
#pragma unroll
    for (int i = 0; i < 2; i++) {
        float* pv = reinterpret_cast<float*>(&v[i]);
        const int base = (tid + i * 256) * 4;
#pragma unroll
        for (int j = 0; j < 4; j++) {
            const float e = (base + j < n) ? __expf(pv[j] - m) : 0.f;
            pv[j] = e;
            sum += e;
        }
    }
    red[tid] = sum;
    __syncthreads();
    for (int off = 128; off > 0; off >>= 1) {
        if (tid < off) red[tid] += red[tid + off];
        __syncthreads();
    }
    const float inv = 1.f / red[0];
#pragma unroll
    for (int i = 0; i < 2; i++) {
        float* pv = reinterpret_cast<float*>(&v[i]);
        float4 o;
        o.x = roundtf(pv[0] * inv);
        o.y = roundtf(pv[1] * inv);
        o.z = roundtf(pv[2] * inv);
        o.w = roundtf(pv[3] * inv);
        s4[tid + i * 256] = o;
    }
}

// ---------------------------------------------------------------------------
extern "C" void kernel_launch(void* const* d_in, const int* in_sizes, int n_in,
                              void* d_out, int out_size)
{
    const float* x  = (const float*)d_in[0];
    const float* Wq = (const float*)d_in[1];
    const float* Wk = (const float*)d_in[2];
    const float* Wv = (const float*)d_in[3];
    float* out = (float*)d_out;

    cudaFuncSetAttribute(proj_mma_pk, cudaFuncAttributeMaxDynamicSharedMemorySize, GSMEM_BYTES);
    cudaFuncSetAttribute(scores_mma,  cudaFuncAttributeMaxDynamicSharedMemorySize, GSMEM_BYTES);
    cudaFuncSetAttribute(pv_mma,      cudaFuncAttributeMaxDynamicSharedMemorySize, HSMEM_BYTES);

    // 0) round+fragment-pack x and W
    pack_x_kernel<<<(MTOT / 16) * (DD / 8) * 32 / 256, 256>>>(x);
    {
        dim3 grid((DD / 8) * (DD / 16) * 32 / 256, 3);
        pack_w_kernel<<<grid, 256>>>(Wq, Wk, Wv);
    }
    {   // 1) QKV projections; epilogue writes Q/K/V in consumer layouts
        dim3 grid(DD / 256, MTOT / 128, 3);
        proj_mma_pk<<<grid, THREADS, GSMEM_BYTES>>>();
    }
    {   // 2) scores = scale * Q K^T (fully packed, causal block skip)
        dim3 grid(TT / 256, TT / 128, BB);
        scores_mma<<<grid, THREADS, GSMEM_BYTES>>>();
    }
    // 3) softmax
    softmax_kernel<<<MTOT, 256>>>();
    {   // 4) out = att V (hybrid, packed V, 128x256)
        dim3 grid(DD / 256, TT / 128, BB);
        pv_mma<<<grid, THREADS, HSMEM_BYTES>>>(out);
    }
}

// round 17
// speedup vs baseline: 1.1014x; 1.1014x over previous
#include <cuda_runtime.h>
#include <cstdint>
#include <math.h>

#define BB 4
#define TT 2048
#define DD 1024
#define MTOT (BB * TT)
#define SCALE (0.03125f)

// ---------------- scratch (no allocations allowed) ----------------
__device__ float g_xpk[(size_t)MTOT * DD];     // x, A-frag packed, tf32
__device__ float g_wpk[(size_t)3 * DD * DD];   // W, B-frag packed, tf32
__device__ float g_qpk[(size_t)MTOT * DD];     // Q, A-frag packed (global m)
__device__ float g_kpk[(size_t)MTOT * DD];     // K, B-frag packed per batch (n=t,k=e)
__device__ float g_vpk[(size_t)MTOT * DD];     // V, B-frag packed per batch (n=e,k=t)
__device__ float g_s[(size_t)BB * TT * TT];    // scores -> att (tf32-rounded)

// ---------------- helpers ----------------
__device__ __forceinline__ uint32_t f2tf(float x) {
    uint32_t u;
    asm("cvt.rna.tf32.f32 %0, %1;" : "=r"(u) : "f"(x));
    return u;
}
__device__ __forceinline__ float roundtf(float x) {
    return __uint_as_float(f2tf(x));
}
__device__ __forceinline__ void mma_tf32(float* c, const uint32_t* a, const uint32_t* b) {
    asm volatile(
        "mma.sync.aligned.m16n8k8.row.col.f32.tf32.tf32.f32 "
        "{%0,%1,%2,%3}, {%4,%5,%6,%7}, {%8,%9}, {%0,%1,%2,%3};"
        : "+f"(c[0]), "+f"(c[1]), "+f"(c[2]), "+f"(c[3])
        : "r"(a[0]), "r"(a[1]), "r"(a[2]), "r"(a[3]), "r"(b[0]), "r"(b[1]));
}
__device__ __forceinline__ uint32_t smem_u32(const void* p) {
    uint32_t a;
    asm("{ .reg .u64 t; cvta.to.shared.u64 t, %1; cvt.u32.u64 %0, t; }" : "=r"(a) : "l"(p));
    return a;
}
__device__ __forceinline__ void cpa16(uint32_t* dst, const float* src) {
    asm volatile("cp.async.cg.shared.global [%0], [%1], 16;"
                 :: "r"(smem_u32(dst)), "l"(src));
}
#define CP_COMMIT() asm volatile("cp.async.commit_group;" ::: "memory")
#define CP_WAIT1()  asm volatile("cp.async.wait_group 1;" ::: "memory")

#define KC 16
#define DSTAGES 3                        // double-chunk stages
#define SA 20
#define A_WORDS (128 * SA)               // 2560 (classic A tile)
#define PK_CHUNK 2048
#define PK_PANEL64 (64 * PK_CHUNK)       // K-range 1024
#define PK_PANEL128 (128 * PK_CHUNK)     // K-range 2048

// packed-layout address helpers (element granularity)
__device__ __forceinline__ size_t apk_off(int m, int k) {
    return ((size_t)(m >> 7) * 64 + (k >> 4)) * PK_CHUNK
         + (size_t)(((k >> 3) & 1) * 1024 + ((m >> 4) & 7) * 128
         + ((m & 7) * 4 + (k & 3)) * 4
         + ((m >> 3) & 1) + 2 * ((k >> 2) & 1));
}
__device__ __forceinline__ size_t bpk_off(int n, int k, int nchunks) {
    return ((size_t)(n >> 7) * nchunks + (k >> 4)) * PK_CHUNK
         + (size_t)(((k >> 3) & 1) * 1024 + ((n >> 4) & 7) * 128
         + ((n & 7) * 4 + (k & 3)) * 4
         + ((k >> 2) & 1) + 2 * ((n >> 3) & 1));
}

// ===================  fully-packed GEMM mainloop (device)  ==================
#define PSTAGE_WORDS (2 * PK_CHUNK)                  // one chunk (A+B)
#define PDSTAGE_WORDS (2 * PSTAGE_WORDS)             // double chunk
#define PSMEM_BYTES (DSTAGES * PDSTAGE_WORDS * 4)    // 98304

// Processes nc chunks (nc even) in pairs: one barrier per 2 chunks.
__device__ __forceinline__ void gemm_pk_main(
    const float* __restrict__ Apk, const float* __restrict__ Bpk,
    int nc, float acc[2][8][4],
    int wm, int wn, int lane)
{
    extern __shared__ uint32_t dsm[];
    const int tid = threadIdx.x;

#pragma unroll
    for (int mi = 0; mi < 2; mi++)
#pragma unroll
        for (int ni = 0; ni < 8; ni++)
#pragma unroll
            for (int j = 0; j < 4; j++) acc[mi][ni][j] = 0.f;

    const int ndc = nc >> 1;

    auto issue2 = [&](int d) {
        uint32_t* st = dsm + (d % DSTAGES) * PDSTAGE_WORDS;
#pragma unroll
        for (int h = 0; h < 2; h++) {
            const int c = 2 * d + h;
            uint32_t* s2 = st + h * PSTAGE_WORDS;
            const float* ap = Apk + (size_t)c * PK_CHUNK + tid * 4;
            cpa16(s2 + tid * 4, ap);
            cpa16(s2 + tid * 4 + 1024, ap + 1024);
            const float* bp = Bpk + (size_t)c * PK_CHUNK + tid * 4;
            cpa16(s2 + PK_CHUNK + tid * 4, bp);
            cpa16(s2 + PK_CHUNK + tid * 4 + 1024, bp + 1024);
        }
        CP_COMMIT();
    };

    issue2(0);
    issue2(1);

    for (int d = 0; d < ndc; d++) {
        CP_WAIT1();
        __syncthreads();
        if (d + 2 < ndc) issue2(d + 2);   // writes slot (d-1): safe post-sync
        const uint32_t* stage = dsm + (d % DSTAGES) * PDSTAGE_WORDS;

#pragma unroll
        for (int h = 0; h < 2; h++) {
            const uint32_t* As = stage + h * PSTAGE_WORDS;
            const uint32_t* Bs = As + PK_CHUNK;
#pragma unroll
            for (int s = 0; s < 2; s++) {
                uint4 af[2], bq[4];
#pragma unroll
                for (int mi = 0; mi < 2; mi++)
                    af[mi] = *reinterpret_cast<const uint4*>(
                        As + s * 1024 + (wm * 2 + mi) * 128 + lane * 4);
#pragma unroll
                for (int p = 0; p < 4; p++)
                    bq[p] = *reinterpret_cast<const uint4*>(
                        Bs + s * 1024 + (wn * 4 + p) * 128 + lane * 4);
#pragma unroll
                for (int mi = 0; mi < 2; mi++)
#pragma unroll
                    for (int ni = 0; ni < 8; ni++) {
                        const uint32_t* bp = reinterpret_cast<const uint32_t*>(&bq[ni >> 1])
                                           + (ni & 1) * 2;
                        mma_tf32(acc[mi][ni], reinterpret_cast<const uint32_t*>(&af[mi]), bp);
                    }
            }
        }
    }
}

// ===================  proj: packed in, packed out  ==========================
__global__ void __launch_bounds__(256, 2)
proj_mma_pk()
{
    const int z = blockIdx.z;
    const float* Apk = g_xpk + (size_t)blockIdx.y * PK_PANEL64;
    const float* Bpk = g_wpk + (size_t)z * (8 * PK_PANEL64) + (size_t)blockIdx.x * PK_PANEL64;

    const int tid = threadIdx.x;
    const int wid = tid >> 5, lane = tid & 31;
    const int g = lane >> 2, t = lane & 3;
    const int wm = wid & 3;
    const int wn = wid >> 2;

    float acc[2][8][4];
    gemm_pk_main(Apk, Bpk, DD / KC, acc, wm, wn, lane);

    const int Mb = blockIdx.y * 128;
    const int Nb = blockIdx.x * 128;
    const int b = blockIdx.y >> 4;
    const int MbL = (blockIdx.y & 15) * 128;

#pragma unroll
    for (int mi = 0; mi < 2; mi++) {
        const int r0 = wm * 32 + mi * 16 + g;
#pragma unroll
        for (int ni = 0; ni < 8; ni++) {
            const int c0 = wn * 64 + ni * 8 + 2 * t;
            float v0 = roundtf(acc[mi][ni][0]);
            float v1 = roundtf(acc[mi][ni][1]);
            float v2 = roundtf(acc[mi][ni][2]);
            float v3 = roundtf(acc[mi][ni][3]);
            if (z == 0) {
                const int m0 = Mb + r0, k0 = Nb + c0;
                g_qpk[apk_off(m0, k0)]         = v0;
                g_qpk[apk_off(m0, k0 + 1)]     = v1;
                g_qpk[apk_off(m0 + 8, k0)]     = v2;
                g_qpk[apk_off(m0 + 8, k0 + 1)] = v3;
            } else if (z == 1) {
                float* base = g_kpk + (size_t)b * TT * DD;
                const int n0 = MbL + r0, k0 = Nb + c0;
                base[bpk_off(n0, k0, 64)]         = v0;
                base[bpk_off(n0, k0 + 1, 64)]     = v1;
                base[bpk_off(n0 + 8, k0, 64)]     = v2;
                base[bpk_off(n0 + 8, k0 + 1, 64)] = v3;
            } else {
                float* base = g_vpk + (size_t)b * TT * DD;
                const int k0 = MbL + r0, n0 = Nb + c0;
                base[bpk_off(n0, k0, 128)]         = v0;
                base[bpk_off(n0 + 1, k0, 128)]     = v1;
                base[bpk_off(n0, k0 + 8, 128)]     = v2;
                base[bpk_off(n0 + 1, k0 + 8, 128)] = v3;
            }
        }
    }
}

// ===================  scores: fully packed  =================================
__global__ void __launch_bounds__(256, 2)
scores_mma()
{
    if (blockIdx.x > blockIdx.y) return;   // fully masked tile
    const int b = blockIdx.z;
    const float* Apk = g_qpk + (size_t)(b * 16 + blockIdx.y) * PK_PANEL64;
    const float* Bpk = g_kpk + (size_t)b * TT * DD + (size_t)blockIdx.x * PK_PANEL64;
    float* C = g_s + (size_t)b * TT * TT
             + (size_t)blockIdx.y * 128 * TT + blockIdx.x * 128;

    const int tid = threadIdx.x;
    const int wid = tid >> 5, lane = tid & 31;
    const int g = lane >> 2, t = lane & 3;
    const int wm = wid & 3;
    const int wn = wid >> 2;

    float acc[2][8][4];
    gemm_pk_main(Apk, Bpk, DD / KC, acc, wm, wn, lane);

#pragma unroll
    for (int mi = 0; mi < 2; mi++) {
        const int r0 = wm * 32 + mi * 16 + g;
#pragma unroll
        for (int ni = 0; ni < 8; ni++) {
            const int col = wn * 64 + ni * 8 + 2 * t;
            float2 v0, v1;
            v0.x = acc[mi][ni][0] * SCALE; v0.y = acc[mi][ni][1] * SCALE;
            v1.x = acc[mi][ni][2] * SCALE; v1.y = acc[mi][ni][3] * SCALE;
            *reinterpret_cast<float2*>(C + (size_t)r0 * TT + col) = v0;
            *reinterpret_cast<float2*>(C + (size_t)(r0 + 8) * TT + col) = v1;
        }
    }
}

// ===================  pv: hybrid-v2, double-chunk  ==========================
#define HSTAGE_WORDS (A_WORDS + PK_CHUNK)            // 4608
#define HDSTAGE_WORDS (2 * HSTAGE_WORDS)             // 9216
#define HSMEM_BYTES (DSTAGES * HDSTAGE_WORDS * 4)    // 110592

__global__ void __launch_bounds__(256, 2)
pv_mma(float* __restrict__ out)
{
    extern __shared__ uint32_t dsm[];
    const int b = blockIdx.z;
    const size_t qb = (size_t)blockIdx.y * 128;
    const float* A = g_s + (size_t)b * TT * TT + qb * TT;      // [q][t]
    const float* Bpk = g_vpk + (size_t)b * TT * DD
                     + (size_t)blockIdx.x * PK_PANEL128;       // e-panel
    float* C = out + (size_t)b * TT * DD + qb * DD + blockIdx.x * 128;

    const int tid = threadIdx.x;
    const int wid = tid >> 5, lane = tid & 31;
    const int g = lane >> 2, t = lane & 3;
    const int wm = wid & 3;
    const int wn = wid >> 2;

    const int rowA = tid >> 2;
    const int kqA = (tid & 3) * 4;

    float acc[2][8][4];
#pragma unroll
    for (int mi = 0; mi < 2; mi++)
#pragma unroll
        for (int ni = 0; ni < 8; ni++)
#pragma unroll
            for (int j = 0; j < 4; j++) acc[mi][ni][j] = 0.f;

    const int ndc = ((blockIdx.y + 1) * 128) >> 5;   // causal bound / 32, >= 4

    auto issue2 = [&](int d) {
        uint32_t* st = dsm + (d % DSTAGES) * HDSTAGE_WORDS;
#pragma unroll
        for (int h = 0; h < 2; h++) {
            const int c = 2 * d + h;
            const int k0 = c * KC;
            uint32_t* s2 = st + h * HSTAGE_WORDS;
            cpa16(s2 + rowA * SA + kqA, A + (size_t)rowA * TT + k0 + kqA);
            cpa16(s2 + (rowA + 64) * SA + kqA, A + (size_t)(rowA + 64) * TT + k0 + kqA);
            uint32_t* bt = s2 + A_WORDS;
            const float* bp = Bpk + (size_t)c * PK_CHUNK + tid * 4;
            cpa16(bt + tid * 4, bp);
            cpa16(bt + tid * 4 + 1024, bp + 1024);
        }
        CP_COMMIT();
    };

    issue2(0);
    issue2(1);

    for (int d = 0; d < ndc; d++) {
        CP_WAIT1();
        __syncthreads();
        if (d + 2 < ndc) issue2(d + 2);
        const uint32_t* stage = dsm + (d % DSTAGES) * HDSTAGE_WORDS;

#pragma unroll
        for (int h = 0; h < 2; h++) {
            const uint32_t* As = stage + h * HSTAGE_WORDS;
            const uint32_t* Bs = As + A_WORDS;
#pragma unroll
            for (int s = 0; s < 2; s++) {
                const int ks = s * 8;
                uint32_t af[2][4];
#pragma unroll
                for (int mi = 0; mi < 2; mi++) {
                    const int r = wm * 32 + mi * 16 + g;
                    af[mi][0] = As[r * SA + ks + t];
                    af[mi][1] = As[(r + 8) * SA + ks + t];
                    af[mi][2] = As[r * SA + ks + t + 4];
                    af[mi][3] = As[(r + 8) * SA + ks + t + 4];
                }
#pragma unroll
                for (int p = 0; p < 4; p++) {
                    uint4 bq = *reinterpret_cast<const uint4*>(
                        Bs + s * 1024 + (wn * 4 + p) * 128 + lane * 4);
                    const uint32_t* bw = reinterpret_cast<const uint32_t*>(&bq);
                    mma_tf32(acc[0][2 * p],     af[0], bw);
                    mma_tf32(acc[0][2 * p + 1], af[0], bw + 2);
                    mma_tf32(acc[1][2 * p],     af[1], bw);
                    mma_tf32(acc[1][2 * p + 1], af[1], bw + 2);
                }
            }
        }
    }

#pragma unroll
    for (int mi = 0; mi < 2; mi++) {
        const int r0 = wm * 32 + mi * 16 + g;
#pragma unroll
        for (int ni = 0; ni < 8; ni++) {
            const int col = wn * 64 + ni * 8 + 2 * t;
            float2 v0, v1;
            v0.x = acc[mi][ni][0]; v0.y = acc[mi][ni][1];
            v1.x = acc[mi][ni][2]; v1.y = acc[mi][ni][3];
            *reinterpret_cast<float2*>(C + (size_t)r0 * DD + col) = v0;
            *reinterpret_cast<float2*>(C + (size_t)(r0 + 8) * DD + col) = v1;
        }
    }
}

// ---------------------------------------------------------------------------
// Merged pre-pack pass: blocks [0, XPB) pack x; rest pack W (z = 0..2).
// ---------------------------------------------------------------------------
#define XPB ((MTOT / 16) * (DD / 8) * 32 / 256)   // 8192
#define WPB ((DD / 8) * (DD / 16) * 32 / 256)     // 1024 per z
__global__ void __launch_bounds__(256)
pack_all_kernel(const float* __restrict__ x,
                const float* __restrict__ Wq, const float* __restrict__ Wk,
                const float* __restrict__ Wv)
{
    const int bi = blockIdx.x;
    if (bi < XPB) {
        const int idx = bi * 256 + threadIdx.x;
        const int lane = idx & 31;
        const int blk = idx >> 5;
        const int kb = blk & 127;
        const int mb = blk >> 7;
        const int m0 = mb * 16, k0 = kb * 8;
        const int g = lane >> 2, t = lane & 3;

        float4 v;
        v.x = roundtf(x[(size_t)(m0 + g) * DD + k0 + t]);
        v.y = roundtf(x[(size_t)(m0 + g + 8) * DD + k0 + t]);
        v.z = roundtf(x[(size_t)(m0 + g) * DD + k0 + t + 4]);
        v.w = roundtf(x[(size_t)(m0 + g + 8) * DD + k0 + t + 4]);

        const int panel = mb >> 3, mbl = mb & 7, chunk = kb >> 1, slab = kb & 1;
        const size_t off = (size_t)(panel * 64 + chunk) * PK_CHUNK
                         + slab * 1024 + mbl * 128 + lane * 4;
        *reinterpret_cast<float4*>(g_xpk + off) = v;
    } else {
        const int r = bi - XPB;
        const int z = r / WPB;
        const float* W = (z == 0) ? Wq : (z == 1) ? Wk : Wv;
        const int idx = (r % WPB) * 256 + threadIdx.x;
        const int lane = idx & 31;
        const int blk = idx >> 5;
        const int kb = blk & 127;
        const int nbp = blk >> 7;
        const int k0 = kb * 8, n0 = nbp * 16;
        const int gn = lane >> 2, tk = lane & 3;

        float4 v;
        v.x = roundtf(W[(size_t)(k0 + tk) * DD + n0 + gn]);
        v.y = roundtf(W[(size_t)(k0 + tk + 4) * DD + n0 + gn]);
        v.z = roundtf(W[(size_t)(k0 + tk) * DD + n0 + 8 + gn]);
        v.w = roundtf(W[(size_t)(k0 + tk + 4) * DD + n0 + 8 + gn]);

        const int panel = nbp >> 3, nbl = nbp & 7, chunk = kb >> 1, slab = kb & 1;
        const size_t off = (size_t)z * (8 * PK_PANEL64)
                         + (size_t)(panel * 64 + chunk) * PK_CHUNK
                         + slab * 1024 + nbl * 128 + lane * 4;
        *reinterpret_cast<float4*>(g_wpk + off) = v;
    }
}

// ---------------------------------------------------------------------------
// Causal softmax, float4 path (in-place on g_s)
// ---------------------------------------------------------------------------
__global__ void __launch_bounds__(256)
softmax_kernel()
{
    const int row = blockIdx.x;
    const int q = row % TT;
    const int n = q + 1;
    float4* s4 = reinterpret_cast<float4*>(g_s + (size_t)row * TT);
    const int tid = threadIdx.x;
    __shared__ float red[256];

    float4 v[2];
    float m = -INFINITY;
#pragma unroll
    for (int i = 0; i < 2; i++) {
        const int idx4 = tid + i * 256;
        v[i] = s4[idx4];
        float* pv = reinterpret_cast<float*>(&v[i]);
        const int base = idx4 * 4;
#pragma unroll
        for (int j = 0; j < 4; j++) {
            if (base + j >= n) pv[j] = -INFINITY;
            else m = fmaxf(m, pv[j]);
        }
    }
    red[tid] = m;
    __syncthreads();
    for (int off = 128; off > 0; off >>= 1) {
        if (tid < off) red[tid] = fmaxf(red[tid], red[tid + off]);
        __syncthreads();
    }
    m = red[0];
    __syncthreads();

    float sum = 0.f;
#pragma unroll
    for (int i = 0; i < 2; i++) {
        float* pv = reinterpret_cast<float*>(&v[i]);
        const int base = (tid + i * 256) * 4;
#pragma unroll
        for (int j = 0; j < 4; j++) {
            const float e = (base + j < n) ? __expf(pv[j] - m) : 0.f;
            pv[j] = e;
            sum += e;
        }
    }
    red[tid] = sum;
    __syncthreads();
    for (int off = 128; off > 0; off >>= 1) {
        if (tid < off) red[tid] += red[tid + off];
        __syncthreads();
    }
    const float inv = 1.f / red[0];
#pragma unroll
    for (int i = 0; i < 2; i++) {
        float* pv = reinterpret_cast<float*>(&v[i]);
        float4 o;
        o.x = roundtf(pv[0] * inv);
        o.y = roundtf(pv[1] * inv);
        o.z = roundtf(pv[2] * inv);
        o.w = roundtf(pv[3] * inv);
        s4[tid + i * 256] = o;
    }
}

// ---------------------------------------------------------------------------
extern "C" void kernel_launch(void* const* d_in, const int* in_sizes, int n_in,
                              void* d_out, int out_size)
{
    const float* x  = (const float*)d_in[0];
    const float* Wq = (const float*)d_in[1];
    const float* Wk = (const float*)d_in[2];
    const float* Wv = (const float*)d_in[3];
    float* out = (float*)d_out;

    cudaFuncSetAttribute(proj_mma_pk, cudaFuncAttributeMaxDynamicSharedMemorySize, PSMEM_BYTES);
    cudaFuncSetAttribute(scores_mma,  cudaFuncAttributeMaxDynamicSharedMemorySize, PSMEM_BYTES);
    cudaFuncSetAttribute(pv_mma,      cudaFuncAttributeMaxDynamicSharedMemorySize, HSMEM_BYTES);

    // 0) round+fragment-pack x and W (single merged launch)
    pack_all_kernel<<<XPB + 3 * WPB, 256>>>(x, Wq, Wk, Wv);
    {   // 1) QKV projections; epilogue writes Q/K/V in consumer layouts
        dim3 grid(DD / 128, MTOT / 128, 3);
        proj_mma_pk<<<grid, 256, PSMEM_BYTES>>>();
    }
    {   // 2) scores = scale * Q K^T (fully packed, causal block skip)
        dim3 grid(TT / 128, TT / 128, BB);
        scores_mma<<<grid, 256, PSMEM_BYTES>>>();
    }
    // 3) softmax
    softmax_kernel<<<MTOT, 256>>>();
    {   // 4) out = att V (hybrid-v2, packed V, double-chunk)
        dim3 grid(DD / 128, TT / 128, BB);
        pv_mma<<<grid, 256, HSMEM_BYTES>>>(out);
    }
}